// round 1
// baseline (speedup 1.0000x reference)
#include <cuda_runtime.h>
#include <math.h>

#define BATCH 128
#define NCAP  4608
#define JDIM  8
#define CDIM  10
#define LDIM  16
#define CL    160          // CDIM*LDIM
#define NPB   64           // n's per block in pass kernel
#define NCHUNKS (NCAP/NPB) // 72

// Scratch (static device globals; no dynamic allocation allowed)
__device__ float g_Wt[NCAP * CL * JDIM];        // [n][cl][j]  ~23.6 MB
__device__ float g_s[BATCH * CDIM * LDIM];      // current s accumulator
__device__ float g_v[BATCH * CDIM * LDIM];      // v used by next pass (v0, then v0+v1)
__device__ float g_vacc[BATCH * CDIM * LDIM];   // running v sum helper

// ---------------------------------------------------------------------------
// Transpose W[n][j][cl] -> Wt[n][cl][j] so each (c,l) row is 8 contiguous
// floats (two float4 smem loads in the pass kernel).
// ---------------------------------------------------------------------------
__global__ void transpose_W_kernel(const float* __restrict__ W) {
    int n  = blockIdx.x;      // 0..4607
    int cl = threadIdx.x;     // 0..159
    const float* Wn = W + (size_t)n * JDIM * CL;
    float v[JDIM];
#pragma unroll
    for (int j = 0; j < JDIM; ++j) v[j] = Wn[j * CL + cl];
    float4* dst = reinterpret_cast<float4*>(g_Wt + ((size_t)n * CL + cl) * JDIM);
    dst[0] = make_float4(v[0], v[1], v[2], v[3]);
    dst[1] = make_float4(v[4], v[5], v[6], v[7]);
}

// ---------------------------------------------------------------------------
// Zero the s accumulator.
// ---------------------------------------------------------------------------
__global__ void zero_s_kernel() {
    int i = blockIdx.x * blockDim.x + threadIdx.x;
    if (i < BATCH * CDIM * LDIM) g_s[i] = 0.0f;
}

// ---------------------------------------------------------------------------
// Routing pass. Block = 320 threads: warp index = c (0..9), lane = local b.
// Each thread owns one (b,c) pair: computes u[b,n,c,0:16] in registers for
// each n in its chunk, (if !FIRST) b-dot against v, softmax over c via smem,
// and accumulates s partial in registers. Ends with 16 atomicAdds.
// ---------------------------------------------------------------------------
template <bool FIRST>
__global__ __launch_bounds__(320) void pass_kernel(const float* __restrict__ x) {
    __shared__ float4 sW4[CL * 2];          // 1280 floats: Wt tile for current n
    __shared__ float4 sx4[32 * 2];          // 32 b's x 8 floats
    __shared__ float  sbdot[CDIM][32];

    const int lane = threadIdx.x & 31;
    const int c    = threadIdx.x >> 5;      // warp id = output capsule
    const int b    = blockIdx.x * 32 + lane;
    const int n0   = blockIdx.y * NPB;

    float vreg[LDIM];
    if (!FIRST) {
#pragma unroll
        for (int l = 0; l < LDIM; ++l)
            vreg[l] = g_v[(b * CDIM + c) * LDIM + l];
    }
    float sacc[LDIM];
#pragma unroll
    for (int l = 0; l < LDIM; ++l) sacc[l] = 0.0f;

    for (int n = n0; n < n0 + NPB; ++n) {
        __syncthreads();   // previous iteration done reading sW/sx/sbdot
        {
            int t = threadIdx.x;
            sW4[t] = reinterpret_cast<const float4*>(g_Wt + (size_t)n * CL * JDIM)[t];
            if (t < 64) {
                int bb = t >> 1, j4 = t & 1;
                sx4[t] = reinterpret_cast<const float4*>(
                    x + ((size_t)(blockIdx.x * 32 + bb) * NCAP + n) * JDIM)[j4];
            }
        }
        __syncthreads();

        const float4 xa = sx4[lane * 2];
        const float4 xb = sx4[lane * 2 + 1];

        float u[LDIM];
#pragma unroll
        for (int l = 0; l < LDIM; ++l) {
            float4 w0 = sW4[(c * LDIM + l) * 2];
            float4 w1 = sW4[(c * LDIM + l) * 2 + 1];
            u[l] = xa.x * w0.x + xa.y * w0.y + xa.z * w0.z + xa.w * w0.w
                 + xb.x * w1.x + xb.y * w1.y + xb.z * w1.z + xb.w * w1.w;
        }

        if (FIRST) {
            // c = softmax(0) = 1/C uniform -> accumulate raw sum; scale later.
#pragma unroll
            for (int l = 0; l < LDIM; ++l) sacc[l] += u[l];
        } else {
            float bd = 0.0f;
#pragma unroll
            for (int l = 0; l < LDIM; ++l) bd += u[l] * vreg[l];
            sbdot[c][lane] = bd;
            __syncthreads();
            float m = -1e30f;
            float vals[CDIM];
#pragma unroll
            for (int cc = 0; cc < CDIM; ++cc) {
                vals[cc] = sbdot[cc][lane];
                m = fmaxf(m, vals[cc]);
            }
            float sum = 0.0f;
#pragma unroll
            for (int cc = 0; cc < CDIM; ++cc) sum += __expf(vals[cc] - m);
            float coef = __expf(bd - m) / sum;
#pragma unroll
            for (int l = 0; l < LDIM; ++l) sacc[l] += coef * u[l];
        }
    }

    float* dst = g_s + (b * CDIM + c) * LDIM;
#pragma unroll
    for (int l = 0; l < LDIM; ++l) atomicAdd(dst + l, sacc[l]);
}

// ---------------------------------------------------------------------------
// squash(s + bias). mode 0: s *= 1/C first, write v -> g_v and g_vacc.
// mode 1: v1 = squash(s+bias); g_v = g_vacc + v1   (b2 = u·(v0+v1))
// mode 2: write squash(s+bias) to output.
// ---------------------------------------------------------------------------
__global__ void squash_kernel(const float* __restrict__ biases, float* __restrict__ out,
                              int mode) {
    int idx = blockIdx.x * blockDim.x + threadIdx.x;   // (b*C + c)
    if (idx >= BATCH * CDIM) return;
    int c = idx % CDIM;
    float scale = (mode == 0) ? (1.0f / CDIM) : 1.0f;
    float s[LDIM];
    float n2 = 0.0f;
#pragma unroll
    for (int l = 0; l < LDIM; ++l) {
        s[l] = g_s[idx * LDIM + l] * scale + biases[c * LDIM + l];
        n2 += s[l] * s[l];
    }
    float nrm = sqrtf(n2);
    float f = n2 / (1.0f + n2) / (nrm + 1e-7f);
    if (mode == 0) {
#pragma unroll
        for (int l = 0; l < LDIM; ++l) {
            float v = f * s[l];
            g_v[idx * LDIM + l] = v;
            g_vacc[idx * LDIM + l] = v;
        }
    } else if (mode == 1) {
#pragma unroll
        for (int l = 0; l < LDIM; ++l) {
            float v = f * s[l];
            g_v[idx * LDIM + l] = g_vacc[idx * LDIM + l] + v;
        }
    } else {
#pragma unroll
        for (int l = 0; l < LDIM; ++l) out[idx * LDIM + l] = f * s[l];
    }
}

extern "C" void kernel_launch(void* const* d_in, const int* in_sizes, int n_in,
                              void* d_out, int out_size) {
    const float* inputs = (const float*)d_in[0];   // [128,12,12,32,8] = [B,N,8]
    const float* W      = (const float*)d_in[1];   // [4608,8,160]
    const float* biases = (const float*)d_in[2];   // [10,16]
    float* out = (float*)d_out;                    // [128,10,16]

    dim3 passGrid(BATCH / 32, NCHUNKS);

    transpose_W_kernel<<<NCAP, CL>>>(W);

    // round 0
    zero_s_kernel<<<(BATCH * CDIM * LDIM + 255) / 256, 256>>>();
    pass_kernel<true><<<passGrid, 320>>>(inputs);
    squash_kernel<<<(BATCH * CDIM + 255) / 256, 256>>>(biases, out, 0);

    // round 1
    zero_s_kernel<<<(BATCH * CDIM * LDIM + 255) / 256, 256>>>();
    pass_kernel<false><<<passGrid, 320>>>(inputs);
    squash_kernel<<<(BATCH * CDIM + 255) / 256, 256>>>(biases, out, 1);

    // round 2 (final)
    zero_s_kernel<<<(BATCH * CDIM * LDIM + 255) / 256, 256>>>();
    pass_kernel<false><<<passGrid, 320>>>(inputs);
    squash_kernel<<<(BATCH * CDIM + 255) / 256, 256>>>(biases, out, 2);
}

// round 2
// speedup vs baseline: 1.1785x; 1.1785x over previous
#include <cuda_runtime.h>
#include <math.h>

#define BATCH 128
#define NCAP  4608
#define JDIM  8
#define CDIM  10
#define LDIM  16
#define CL    160            // CDIM*LDIM
#define NPB   64             // n's per block in pass kernel
#define NCHUNKS (NCAP/NPB)   // 72

typedef unsigned long long ull;

// Scratch (static device globals; no dynamic allocation allowed)
__device__ __align__(16) float g_Wt[NCAP * CL * JDIM];      // [n][c][j][l]  ~23.6 MB
__device__ __align__(16) float g_s[BATCH * CDIM * LDIM];    // s accumulator
__device__ __align__(16) float g_v[BATCH * CDIM * LDIM];    // v for next pass (v0, then v0+v1)
__device__ __align__(16) float g_vacc[BATCH * CDIM * LDIM]; // running v sum

// ---- f32x2 packed-math helpers (FFMA2 path, PTX-only) ----------------------
__device__ __forceinline__ ull pk2(float a, float b) {
    ull r; asm("mov.b64 %0,{%1,%2};" : "=l"(r) : "f"(a), "f"(b)); return r;
}
__device__ __forceinline__ ull fma2(ull a, ull b, ull c) {
    ull d; asm("fma.rn.f32x2 %0,%1,%2,%3;" : "=l"(d) : "l"(a), "l"(b), "l"(c)); return d;
}
__device__ __forceinline__ ull add2(ull a, ull b) {
    ull d; asm("add.rn.f32x2 %0,%1,%2;" : "=l"(d) : "l"(a), "l"(b)); return d;
}
__device__ __forceinline__ float lo2(ull a) {
    float f; asm("{ .reg .b32 h; mov.b64 {%0,h}, %1; }" : "=f"(f) : "l"(a)); return f;
}
__device__ __forceinline__ float hi2(ull a) {
    float f; asm("{ .reg .b32 l; mov.b64 {l,%0}, %1; }" : "=f"(f) : "l"(a)); return f;
}

// ---------------------------------------------------------------------------
// Transpose W[n][j][c*16+l] -> Wt[n][c][j][l]: l-pairs contiguous for f32x2.
// ---------------------------------------------------------------------------
__global__ void transpose_W_kernel(const float* __restrict__ W) {
    int n  = blockIdx.x;          // 0..4607
    int t  = threadIdx.x;         // 0..159 = c*16+l
    int c  = t >> 4, l = t & 15;
    const float* Wn = W + (size_t)n * JDIM * CL;
    float* dst = g_Wt + (size_t)n * CL * JDIM;
#pragma unroll
    for (int j = 0; j < JDIM; ++j)
        dst[(c * JDIM + j) * LDIM + l] = Wn[j * CL + t];
}

__global__ void zero_s_kernel() {
    int i = blockIdx.x * blockDim.x + threadIdx.x;
    if (i < BATCH * CDIM * LDIM) g_s[i] = 0.0f;
}

// ---------------------------------------------------------------------------
// Routing pass. 640 threads: warp w -> c = w%10, b-group = w/10.
// Thread owns (b, c). Groups of 2 n's per smem tile. All inner math in f32x2.
// ---------------------------------------------------------------------------
template <bool FIRST>
__global__ __launch_bounds__(640, 1) void pass_kernel(const float* __restrict__ x) {
    __shared__ float sW[2 * CL * JDIM];     // 2 tiles, [i][c][j][l]   10 KB
    __shared__ float sx[2][64 * 9];         // pad-9: conflict-free     4.5 KB
    __shared__ float sE[2][CDIM][64];       // exp(bd)                  5 KB

    const int tid  = threadIdx.x;
    const int lane = tid & 31;
    const int wid  = tid >> 5;              // 0..19
    const int c    = wid % CDIM;
    const int bl   = (wid / CDIM) * 32 + lane;   // 0..63 local b
    const int b    = blockIdx.x * 64 + bl;
    const int n0   = blockIdx.y * NPB;

    ull v2[8];
    if (!FIRST) {
        const ull* vp = reinterpret_cast<const ull*>(g_v) + (b * CDIM + c) * 8;
#pragma unroll
        for (int p = 0; p < 8; ++p) v2[p] = vp[p];
    }
    ull sacc2[8];
#pragma unroll
    for (int p = 0; p < 8; ++p) sacc2[p] = 0ull;

    for (int g = 0; g < NPB / 2; ++g) {
        const int n = n0 + g * 2;
        __syncthreads();    // previous group done with sW/sx/sE
        // stage W tiles: 2*1280 floats = 640 float4, one per thread
        reinterpret_cast<float4*>(sW)[tid] =
            reinterpret_cast<const float4*>(g_Wt + (size_t)n * CL * JDIM)[tid];
        // stage x: 2 n * 64 b * 8 j floats, scalar stores into pad-9 layout
        if (tid < 512) {
            int i  = tid >> 8;            // n sub-index
            int bb = (tid >> 2) & 63;     // local b
            int j2 = (tid & 3) * 2;       // even j
            const float2 xv = *reinterpret_cast<const float2*>(
                x + ((size_t)(blockIdx.x * 64 + bb) * NCAP + n + i) * JDIM + j2);
            sx[i][bb * 9 + j2]     = xv.x;
            sx[i][bb * 9 + j2 + 1] = xv.y;
        }
        __syncthreads();

        ull u2[2][8];
        float e_own[2];
#pragma unroll
        for (int i = 0; i < 2; ++i) {
            const float* wbase = sW + i * CL * JDIM + c * JDIM * LDIM;
#pragma unroll
            for (int p = 0; p < 8; ++p) u2[i][p] = 0ull;
#pragma unroll
            for (int j = 0; j < JDIM; ++j) {
                float xs = sx[i][bl * 9 + j];
                ull x2 = pk2(xs, xs);
                const ulonglong2* w =
                    reinterpret_cast<const ulonglong2*>(wbase + j * LDIM);
                ulonglong2 wa = w[0], wb = w[1], wc = w[2], wd = w[3];
                u2[i][0] = fma2(wa.x, x2, u2[i][0]);
                u2[i][1] = fma2(wa.y, x2, u2[i][1]);
                u2[i][2] = fma2(wb.x, x2, u2[i][2]);
                u2[i][3] = fma2(wb.y, x2, u2[i][3]);
                u2[i][4] = fma2(wc.x, x2, u2[i][4]);
                u2[i][5] = fma2(wc.y, x2, u2[i][5]);
                u2[i][6] = fma2(wd.x, x2, u2[i][6]);
                u2[i][7] = fma2(wd.y, x2, u2[i][7]);
            }
            if (!FIRST) {
                ull bd2 = 0ull;
#pragma unroll
                for (int p = 0; p < 8; ++p) bd2 = fma2(u2[i][p], v2[p], bd2);
                float bd = lo2(bd2) + hi2(bd2);
                // |bd| is small (<~10): softmax without max-subtraction is safe
                e_own[i] = __expf(bd);
                sE[i][c][bl] = e_own[i];
            }
        }

        if (FIRST) {
            // softmax(0) = 1/C uniform; accumulate raw sum, scale in squash.
#pragma unroll
            for (int i = 0; i < 2; ++i)
#pragma unroll
                for (int p = 0; p < 8; ++p) sacc2[p] = add2(sacc2[p], u2[i][p]);
        } else {
            __syncthreads();
#pragma unroll
            for (int i = 0; i < 2; ++i) {
                float sum = 0.0f;
#pragma unroll
                for (int cc = 0; cc < CDIM; ++cc) sum += sE[i][cc][bl];
                float coef = __fdividef(e_own[i], sum);
                ull c2 = pk2(coef, coef);
#pragma unroll
                for (int p = 0; p < 8; ++p) sacc2[p] = fma2(u2[i][p], c2, sacc2[p]);
            }
        }
    }

    float* dst = g_s + (b * CDIM + c) * LDIM;
#pragma unroll
    for (int p = 0; p < 8; ++p) {
        atomicAdd(dst + 2 * p,     lo2(sacc2[p]));
        atomicAdd(dst + 2 * p + 1, hi2(sacc2[p]));
    }
}

// ---------------------------------------------------------------------------
// squash(s + bias). mode 0: s *= 1/C, write v -> g_v,g_vacc.  mode 1:
// g_v = g_vacc + squash(s+bias)  (since b_2 = u.(v0+v1)).  mode 2: write out.
// Modes 0/1 also re-zero g_s for the next pass.
// ---------------------------------------------------------------------------
__global__ void squash_kernel(const float* __restrict__ biases, float* __restrict__ out,
                              int mode) {
    int idx = blockIdx.x * blockDim.x + threadIdx.x;   // (b*C + c)
    if (idx >= BATCH * CDIM) return;
    int c = idx % CDIM;
    float scale = (mode == 0) ? (1.0f / CDIM) : 1.0f;
    float s[LDIM];
    float n2 = 0.0f;
#pragma unroll
    for (int l = 0; l < LDIM; ++l) {
        s[l] = g_s[idx * LDIM + l] * scale + biases[c * LDIM + l];
        n2 += s[l] * s[l];
    }
    float nrm = sqrtf(n2);
    float f = n2 / (1.0f + n2) / (nrm + 1e-7f);
    if (mode == 0) {
#pragma unroll
        for (int l = 0; l < LDIM; ++l) {
            float v = f * s[l];
            g_v[idx * LDIM + l] = v;
            g_vacc[idx * LDIM + l] = v;
            g_s[idx * LDIM + l] = 0.0f;
        }
    } else if (mode == 1) {
#pragma unroll
        for (int l = 0; l < LDIM; ++l) {
            float v = f * s[l];
            g_v[idx * LDIM + l] = g_vacc[idx * LDIM + l] + v;
            g_s[idx * LDIM + l] = 0.0f;
        }
    } else {
#pragma unroll
        for (int l = 0; l < LDIM; ++l) out[idx * LDIM + l] = f * s[l];
    }
}

extern "C" void kernel_launch(void* const* d_in, const int* in_sizes, int n_in,
                              void* d_out, int out_size) {
    const float* inputs = (const float*)d_in[0];   // [128,12,12,32,8] = [B,N,8]
    const float* W      = (const float*)d_in[1];   // [4608,8,160]
    const float* biases = (const float*)d_in[2];   // [10,16]
    float* out = (float*)d_out;                    // [128,10,16]

    dim3 passGrid(BATCH / 64, NCHUNKS);            // (2, 72) = 144 blocks

    transpose_W_kernel<<<NCAP, CL>>>(W);
    zero_s_kernel<<<(BATCH * CDIM * LDIM + 255) / 256, 256>>>();

    pass_kernel<true><<<passGrid, 640>>>(inputs);
    squash_kernel<<<(BATCH * CDIM + 255) / 256, 256>>>(biases, out, 0);

    pass_kernel<false><<<passGrid, 640>>>(inputs);
    squash_kernel<<<(BATCH * CDIM + 255) / 256, 256>>>(biases, out, 1);

    pass_kernel<false><<<passGrid, 640>>>(inputs);
    squash_kernel<<<(BATCH * CDIM + 255) / 256, 256>>>(biases, out, 2);
}